// round 8
// baseline (speedup 1.0000x reference)
#include <cuda_runtime.h>
#include <cstdint>

#define HH 128
#define WW 192
#define CC_TOT 256
#define BB 8
#define TILE_W 32
#define TILE_H 16
#define HALO_H 24
#define CHUNK 4
#define NCHUNK (CC_TOT / CHUNK)
#define NT 256
#define PLANE ((size_t)HH * WW)

#define HROW 176                      // 44 floats/row (40 used, 4 pad) - bank-conflict-free at X=8
#define CROW 144                      // 36 floats/row (32 used)
#define PSEC (HALO_H * HROW)          // 4224
#define CSEC (TILE_H * CROW)          // 2304
#define PREV_BUF (CHUNK * PSEC)       // 16896
#define CURR_BUF (CHUNK * CSEC)       // 9216
#define SM_PREV 0
#define SM_CURR (3 * PREV_BUF)        // 50688
#define SM_SSP  (SM_CURR + 3 * CURR_BUF)  // 78336
#define SMEM_BYTES (SM_SSP + PSEC)        // 82560 -> 2 CTAs/SM

typedef unsigned long long u64;

__device__ __forceinline__ void F2(u64 &d, u64 a, u64 b) {
    asm("fma.rn.f32x2 %0, %1, %2, %0;" : "+l"(d) : "l"(a), "l"(b));
}
__device__ __forceinline__ u64 M2(u64 a, u64 b) {
    u64 d; asm("mul.rn.f32x2 %0, %1, %2;" : "=l"(d) : "l"(a), "l"(b)); return d;
}
__device__ __forceinline__ u64 PK(unsigned a, unsigned b) {
    u64 d; asm("mov.b64 %0, {%1, %2};" : "=l"(d) : "r"(a), "r"(b)); return d;
}
__device__ __forceinline__ unsigned LOW(u64 a) {
    unsigned l, h; asm("mov.b64 {%0, %1}, %2;" : "=r"(l), "=r"(h) : "l"(a)); return l;
}
__device__ __forceinline__ unsigned HIW(u64 a) {
    unsigned l, h; asm("mov.b64 {%0, %1}, %2;" : "=r"(l), "=r"(h) : "l"(a)); return h;
}
__device__ __forceinline__ float FL(u64 a) { return __uint_as_float(LOW(a)); }
__device__ __forceinline__ float FH(u64 a) { return __uint_as_float(HIW(a)); }
__device__ __forceinline__ void cp16(uint32_t dst, const void* src, int szbytes) {
    asm volatile("cp.async.cg.shared.global [%0], [%1], 16, %2;\n"
                 :: "r"(dst), "l"(src), "r"(szbytes) : "memory");
}
__device__ __forceinline__ ulonglong2 LD2(const void* p) {
    return *reinterpret_cast<const ulonglong2*>(p);
}
__device__ __forceinline__ u64 LD1(const void* p) {
    return *reinterpret_cast<const u64*>(p);
}
__device__ __forceinline__ float GRD(float v) { return v > 0.f ? rsqrtf(v) : 0.f; }

__global__ void __launch_bounds__(NT, 2)
corr_kernel(const float* __restrict__ curr, const float* __restrict__ prev,
            float* __restrict__ out)
{
    extern __shared__ char smem[];

    const int tid = threadIdx.x;
    const int grp = tid >> 6;          // 4 groups of 64 threads
    const int gt  = tid & 63;
    const int xg  = gt & 3;            // 4 x-groups of 8 pixels
    const int ty  = gt >> 2;           // 16 rows
    const int x0  = blockIdx.x * TILE_W;
    const int y0  = blockIdx.y * TILE_H;
    const int bb  = blockIdx.z;

    const char* currB = (const char*)(curr + (size_t)bb * CC_TOT * PLANE);
    const char* prevB = (const char*)(prev + (size_t)bb * CC_TOT * PLANE);
    const uint32_t smA = (uint32_t)__cvta_generic_to_shared(smem);

    // ---- staging precompute ----
    const int psy = tid / 10, psx = tid - psy * 10;   // 240 f4 slots (24 rows x 10)
    const int pgy = y0 - 4 + psy, pgx = x0 - 4 + psx * 4;
    const bool doP = (tid < 240);
    const bool pok = doP && ((unsigned)pgy < HH) && ((unsigned)pgx < WW);
    const int pOff = pok ? (pgy * WW + pgx) * 4 : 0;
    const int psz  = pok ? 16 : 0;
    const uint32_t pRel = (uint32_t)(psy * HROW + psx * 16);
    const bool doC = (tid >= 128);
    const int cslot = tid - 128;
    const int csy = cslot >> 3, csx = cslot & 7;
    const int cOff = ((y0 + csy) * WW + x0 + csx * 4) * 4;
    const uint32_t cRel = (uint32_t)(csy * CROW + csx * 16);

    // ---- boundary-sq fallback: 112 slots over G0(32)/G1(32)/G3(48) ----
    int fbj = -1;
    if (grp == 0)      { if (gt < 32) fbj = gt; }
    else if (grp == 1) { if (gt < 32) fbj = 32 + gt; }
    else if (grp == 3) { if (gt < 48) fbj = 64 + gt; }
    const bool doFB = (fbj >= 0);
    int fbRow = 0, fbCol = 0;
    if (fbj >= 0) {
        if (fbj < 40)      { fbRow = fbj / 10; fbCol = fbj - fbRow * 10; }
        else if (fbj < 80) { int i = fbj - 40; fbRow = 20 + i / 10; fbCol = i - (i / 10) * 10; }
        else               { int i = fbj - 80; fbRow = 4 + (i >> 1); fbCol = (i & 1) ? 9 : 0; }
    }
    const uint32_t fbOff = (uint32_t)(fbRow * HROW + fbCol * 16);

    // ---- accumulators ----
    // per offset: 4 u64 (pixel pairs 01,23,45,67)
    // G0: [0..4]=dy-4 (o0..4), [5..7]=dy-1 (o10..12)
    // G1: [0..4]=dy-2 (o5..9), [5..7]=dy+1 (o20..22)
    // G2: [0..6]=dy0 (o13..19), [7..8]=dy+2 dx{-4,-2} (o23,o24)
    // G3: [0..4]=dy+4 (o28..32), [5..7]=dy+2 dx{0,2,4} (o25,o26,o27)
    u64 acc[36];
    #pragma unroll
    for (int i = 0; i < 36; i++) acc[i] = 0ull;
    u64 ssq01 = 0ull, ssq23 = 0ull, ssq45 = 0ull, ssq67 = 0ull;
    u64 sq0 = 0ull, sq1 = 0ull, sq2 = 0ull, sq3 = 0ull;   // G2 interior prev-sq
    u64 fbA = 0ull, fbB = 0ull;                            // boundary prev-sq

    auto issue = [&](const char* srcP, const char* srcC, uint32_t dP, uint32_t dC) {
        #pragma unroll
        for (int cc = 0; cc < CHUNK; cc++) {
            const size_t so = (size_t)cc * PLANE * 4;
            if (doP) cp16(dP + cc * PSEC + pRel, srcP + so + pOff, psz);
            if (doC) cp16(dC + cc * CSEC + cRel, srcC + so + cOff, 16);
        }
        asm volatile("cp.async.commit_group;\n" ::: "memory");
    };

    issue(prevB, currB, smA + SM_PREV, smA + SM_CURR);
    issue(prevB + (size_t)CHUNK * PLANE * 4, currB + (size_t)CHUNK * PLANE * 4,
          smA + SM_PREV + PREV_BUF, smA + SM_CURR + CURR_BUF);

    const char* srcPs = prevB + (size_t)2 * CHUNK * PLANE * 4;
    const char* srcCs = currB + (size_t)2 * CHUNK * PLANE * 4;
    int bC = 0, bS = 2;

    const int tyOff = ty * HROW + xg * 32;   // halo row base (float col = xg*8)
    const int cvOff = ty * CROW + xg * 32;

// full row: 5 offsets (dx -4,-2,0,2,4), 4 quads
#define FROW(O, RB) do { \
    const ulonglong2 q0 = LD2(RB), q1 = LD2((RB) + 16), q2 = LD2((RB) + 32), q3 = LD2((RB) + 48); \
    F2(acc[(O)*4+0],cv01,q0.x); F2(acc[(O)*4+1],cv23,q0.y); F2(acc[(O)*4+2],cv45,q1.x); F2(acc[(O)*4+3],cv67,q1.y); \
    F2(acc[(O)*4+4],cv01,q0.y); F2(acc[(O)*4+5],cv23,q1.x); F2(acc[(O)*4+6],cv45,q1.y); F2(acc[(O)*4+7],cv67,q2.x); \
    F2(acc[(O)*4+8],cv01,q1.x); F2(acc[(O)*4+9],cv23,q1.y); F2(acc[(O)*4+10],cv45,q2.x); F2(acc[(O)*4+11],cv67,q2.y); \
    F2(acc[(O)*4+12],cv01,q1.y); F2(acc[(O)*4+13],cv23,q2.x); F2(acc[(O)*4+14],cv45,q2.y); F2(acc[(O)*4+15],cv67,q3.x); \
    F2(acc[(O)*4+16],cv01,q2.x); F2(acc[(O)*4+17],cv23,q2.y); F2(acc[(O)*4+18],cv45,q3.x); F2(acc[(O)*4+19],cv67,q3.y); \
} while (0)

// mid row: 3 offsets (dx -1,0,1); loads f3, q1, q2, f12
#define MROW(O, RB) do { \
    const unsigned f3 = *(const unsigned*)((RB) + 12); \
    const ulonglong2 q1 = LD2((RB) + 16), q2 = LD2((RB) + 32); \
    const unsigned f12 = *(const unsigned*)((RB) + 48); \
    const u64 P34 = PK(f3, LOW(q1.x)),      P56 = PK(HIW(q1.x), LOW(q1.y)); \
    const u64 P78 = PK(HIW(q1.y), LOW(q2.x)), P9A = PK(HIW(q2.x), LOW(q2.y)); \
    const u64 PBC = PK(HIW(q2.y), f12); \
    F2(acc[(O)*4+0],cv01,P34);  F2(acc[(O)*4+1],cv23,P56);  F2(acc[(O)*4+2],cv45,P78);  F2(acc[(O)*4+3],cv67,P9A); \
    F2(acc[(O)*4+4],cv01,q1.x); F2(acc[(O)*4+5],cv23,q1.y); F2(acc[(O)*4+6],cv45,q2.x); F2(acc[(O)*4+7],cv67,q2.y); \
    F2(acc[(O)*4+8],cv01,P56);  F2(acc[(O)*4+9],cv23,P78);  F2(acc[(O)*4+10],cv45,P9A); F2(acc[(O)*4+11],cv67,PBC); \
} while (0)

#define PREAMBLE \
    const char* secB = pbuf + cc * PSEC; \
    const char* rowB = secB + tyOff; \
    const char* cvP  = cbuf + cc * CSEC + cvOff; \
    const ulonglong2 CA = LD2(cvP), CB = LD2(cvP + 16); \
    const u64 cv01 = CA.x, cv23 = CA.y, cv45 = CB.x, cv67 = CB.y; \
    F2(ssq01, cv01, cv01); F2(ssq23, cv23, cv23); F2(ssq45, cv45, cv45); F2(ssq67, cv67, cv67);

    #pragma unroll 1
    for (int k = 0; k < NCHUNK; k++) {
        if (k < NCHUNK - 1) asm volatile("cp.async.wait_group 1;\n" ::: "memory");
        else                asm volatile("cp.async.wait_group 0;\n" ::: "memory");
        __syncthreads();

        if (k < NCHUNK - 2) {
            issue(srcPs, srcCs, smA + SM_PREV + bS * PREV_BUF, smA + SM_CURR + bS * CURR_BUF);
            srcPs += (size_t)CHUNK * PLANE * 4;
            srcCs += (size_t)CHUNK * PLANE * 4;
            bS = (bS == 2) ? 0 : bS + 1;
        }

        const char* pbuf = smem + SM_PREV + bC * PREV_BUF;
        const char* cbuf = smem + SM_CURR + bC * CURR_BUF;

        if (grp == 0) {
            #pragma unroll
            for (int cc = 0; cc < CHUNK; cc++) {
                PREAMBLE
                if (doFB) { const ulonglong2 v = LD2(secB + fbOff); F2(fbA, v.x, v.x); F2(fbB, v.y, v.y); }
                FROW(0, rowB);          // dy=-4: o0..4
                MROW(5, rowB + 528);    // dy=-1: o10..12
            }
        } else if (grp == 1) {
            #pragma unroll
            for (int cc = 0; cc < CHUNK; cc++) {
                PREAMBLE
                if (doFB) { const ulonglong2 v = LD2(secB + fbOff); F2(fbA, v.x, v.x); F2(fbB, v.y, v.y); }
                FROW(0, rowB + 352);    // dy=-2: o5..9
                MROW(5, rowB + 880);    // dy=+1: o20..22
            }
        } else if (grp == 2) {
            #pragma unroll
            for (int cc = 0; cc < CHUNK; cc++) {
                PREAMBLE
                {   // dy=0: 7 offsets (o13..19) + interior prev-sq
                    const char* rb = rowB + 704;
                    const ulonglong2 q0 = LD2(rb), q1 = LD2(rb + 16), q2 = LD2(rb + 32), q3 = LD2(rb + 48);
                    F2(sq0, q1.x, q1.x); F2(sq1, q1.y, q1.y); F2(sq2, q2.x, q2.x); F2(sq3, q2.y, q2.y);
                    const u64 P34 = PK(HIW(q0.y), LOW(q1.x)), P56 = PK(HIW(q1.x), LOW(q1.y));
                    const u64 P78 = PK(HIW(q1.y), LOW(q2.x)), P9A = PK(HIW(q2.x), LOW(q2.y));
                    const u64 PBC = PK(HIW(q2.y), LOW(q3.x));
                    F2(acc[0],cv01,q0.x);  F2(acc[1],cv23,q0.y);  F2(acc[2],cv45,q1.x);  F2(acc[3],cv67,q1.y);
                    F2(acc[4],cv01,q0.y);  F2(acc[5],cv23,q1.x);  F2(acc[6],cv45,q1.y);  F2(acc[7],cv67,q2.x);
                    F2(acc[8],cv01,P34);   F2(acc[9],cv23,P56);   F2(acc[10],cv45,P78);  F2(acc[11],cv67,P9A);
                    F2(acc[12],cv01,q1.x); F2(acc[13],cv23,q1.y); F2(acc[14],cv45,q2.x); F2(acc[15],cv67,q2.y);
                    F2(acc[16],cv01,P56);  F2(acc[17],cv23,P78);  F2(acc[18],cv45,P9A);  F2(acc[19],cv67,PBC);
                    F2(acc[20],cv01,q1.y); F2(acc[21],cv23,q2.x); F2(acc[22],cv45,q2.y); F2(acc[23],cv67,q3.x);
                    F2(acc[24],cv01,q2.x); F2(acc[25],cv23,q2.y); F2(acc[26],cv45,q3.x); F2(acc[27],cv67,q3.y);
                }
                {   // dy=+2 dx{-4,-2}: o23,o24
                    const char* rb = rowB + 1056;
                    const ulonglong2 q0 = LD2(rb), q1 = LD2(rb + 16);
                    const u64 q2lo = LD1(rb + 32);
                    F2(acc[28],cv01,q0.x); F2(acc[29],cv23,q0.y); F2(acc[30],cv45,q1.x); F2(acc[31],cv67,q1.y);
                    F2(acc[32],cv01,q0.y); F2(acc[33],cv23,q1.x); F2(acc[34],cv45,q1.y); F2(acc[35],cv67,q2lo);
                }
            }
        } else {
            #pragma unroll
            for (int cc = 0; cc < CHUNK; cc++) {
                PREAMBLE
                if (doFB) { const ulonglong2 v = LD2(secB + fbOff); F2(fbA, v.x, v.x); F2(fbB, v.y, v.y); }
                FROW(0, rowB + 1408);   // dy=+4: o28..32
                {   // dy=+2 dx{0,2,4}: o25,o26,o27
                    const char* rb = rowB + 1056;
                    const ulonglong2 q1 = LD2(rb + 16), q2 = LD2(rb + 32), q3 = LD2(rb + 48);
                    F2(acc[20],cv01,q1.x); F2(acc[21],cv23,q1.y); F2(acc[22],cv45,q2.x); F2(acc[23],cv67,q2.y);
                    F2(acc[24],cv01,q1.y); F2(acc[25],cv23,q2.x); F2(acc[26],cv45,q2.y); F2(acc[27],cv67,q3.x);
                    F2(acc[28],cv01,q2.x); F2(acc[29],cv23,q2.y); F2(acc[30],cv45,q3.x); F2(acc[31],cv67,q3.y);
                }
            }
        }
        bC = (bC == 2) ? 0 : bC + 1;
    }

    // ---- epilogue: prev inverse norms into ssp ----
    {
        char* sspB = smem + SM_SSP;
        if (grp == 2) {   // interior: rows 4..19, float cols 4..35
            float4 w0, w1;
            w0.x = GRD(FL(sq0)); w0.y = GRD(FH(sq0)); w0.z = GRD(FL(sq1)); w0.w = GRD(FH(sq1));
            w1.x = GRD(FL(sq2)); w1.y = GRD(FH(sq2)); w1.z = GRD(FL(sq3)); w1.w = GRD(FH(sq3));
            char* dst = sspB + (ty + 4) * HROW + xg * 32 + 16;
            *(float4*)dst = w0;
            *(float4*)(dst + 16) = w1;
        }
        if (doFB) {
            float4 w;
            w.x = GRD(FL(fbA)); w.y = GRD(FH(fbA)); w.z = GRD(FL(fbB)); w.w = GRD(FH(fbB));
            *(float4*)(sspB + fbOff) = w;
        }
    }
    __syncthreads();

    u64 inv01, inv23, inv45, inv67;
    {
        const float n0 = rsqrtf(FL(ssq01)), n1 = rsqrtf(FH(ssq01));
        const float n2 = rsqrtf(FL(ssq23)), n3 = rsqrtf(FH(ssq23));
        const float n4 = rsqrtf(FL(ssq45)), n5 = rsqrtf(FH(ssq45));
        const float n6 = rsqrtf(FL(ssq67)), n7 = rsqrtf(FH(ssq67));
        inv01 = PK(__float_as_uint(n0), __float_as_uint(n1));
        inv23 = PK(__float_as_uint(n2), __float_as_uint(n3));
        inv45 = PK(__float_as_uint(n4), __float_as_uint(n5));
        inv67 = PK(__float_as_uint(n6), __float_as_uint(n7));
    }

    const char* srow = smem + SM_SSP + tyOff;
    char* outBase = (char*)(out + ((size_t)bb * 33 * HH + (y0 + ty)) * WW + x0 + xg * 8);

#define OST(PL, O, B0, B1, B2, B3) do { \
    ulonglong2 r0, r1; \
    r0.x = M2(M2(acc[(O)*4+0], inv01), (B0)); \
    r0.y = M2(M2(acc[(O)*4+1], inv23), (B1)); \
    r1.x = M2(M2(acc[(O)*4+2], inv45), (B2)); \
    r1.y = M2(M2(acc[(O)*4+3], inv67), (B3)); \
    char* _op = outBase + (size_t)(PL) * (PLANE * 4); \
    *(ulonglong2*)_op = r0; \
    *(ulonglong2*)(_op + 16) = r1; \
} while (0)

#define EFROW(SR, PL, O) do { \
    const ulonglong2 q0 = LD2(srow + (SR)), q1 = LD2(srow + (SR) + 16); \
    const ulonglong2 q2 = LD2(srow + (SR) + 32), q3 = LD2(srow + (SR) + 48); \
    OST((PL)+0, (O)+0, q0.x, q0.y, q1.x, q1.y); \
    OST((PL)+1, (O)+1, q0.y, q1.x, q1.y, q2.x); \
    OST((PL)+2, (O)+2, q1.x, q1.y, q2.x, q2.y); \
    OST((PL)+3, (O)+3, q1.y, q2.x, q2.y, q3.x); \
    OST((PL)+4, (O)+4, q2.x, q2.y, q3.x, q3.y); \
} while (0)

#define EMROW(SR, PL, O) do { \
    const unsigned f3 = *(const unsigned*)(srow + (SR) + 12); \
    const ulonglong2 q1 = LD2(srow + (SR) + 16), q2 = LD2(srow + (SR) + 32); \
    const unsigned f12 = *(const unsigned*)(srow + (SR) + 48); \
    const u64 P34 = PK(f3, LOW(q1.x)),        P56 = PK(HIW(q1.x), LOW(q1.y)); \
    const u64 P78 = PK(HIW(q1.y), LOW(q2.x)), P9A = PK(HIW(q2.x), LOW(q2.y)); \
    const u64 PBC = PK(HIW(q2.y), f12); \
    OST((PL)+0, (O)+0, P34, P56, P78, P9A); \
    OST((PL)+1, (O)+1, q1.x, q1.y, q2.x, q2.y); \
    OST((PL)+2, (O)+2, P56, P78, P9A, PBC); \
} while (0)

    if (grp == 0) {
        EFROW(0, 0, 0);        // dy=-4: o0..4
        EMROW(528, 10, 5);     // dy=-1: o10..12
    } else if (grp == 1) {
        EFROW(352, 5, 0);      // dy=-2: o5..9
        EMROW(880, 20, 5);     // dy=+1: o20..22
    } else if (grp == 2) {
        {   // dy=0: o13..19
            const ulonglong2 q0 = LD2(srow + 704), q1 = LD2(srow + 720);
            const ulonglong2 q2 = LD2(srow + 736), q3 = LD2(srow + 752);
            const u64 P34 = PK(HIW(q0.y), LOW(q1.x)), P56 = PK(HIW(q1.x), LOW(q1.y));
            const u64 P78 = PK(HIW(q1.y), LOW(q2.x)), P9A = PK(HIW(q2.x), LOW(q2.y));
            const u64 PBC = PK(HIW(q2.y), LOW(q3.x));
            OST(13, 0, q0.x, q0.y, q1.x, q1.y);
            OST(14, 1, q0.y, q1.x, q1.y, q2.x);
            OST(15, 2, P34, P56, P78, P9A);
            OST(16, 3, q1.x, q1.y, q2.x, q2.y);
            OST(17, 4, P56, P78, P9A, PBC);
            OST(18, 5, q1.y, q2.x, q2.y, q3.x);
            OST(19, 6, q2.x, q2.y, q3.x, q3.y);
        }
        {   // dy=+2 dx{-4,-2}: o23,o24
            const ulonglong2 q0 = LD2(srow + 1056), q1 = LD2(srow + 1072);
            const u64 q2lo = LD1(srow + 1088);
            OST(23, 7, q0.x, q0.y, q1.x, q1.y);
            OST(24, 8, q0.y, q1.x, q1.y, q2lo);
        }
    } else {
        EFROW(1408, 28, 0);    // dy=+4: o28..32
        {   // dy=+2 dx{0,2,4}: o25,o26,o27
            const ulonglong2 q1 = LD2(srow + 1072), q2 = LD2(srow + 1088), q3 = LD2(srow + 1104);
            OST(25, 5, q1.x, q1.y, q2.x, q2.y);
            OST(26, 6, q1.y, q2.x, q2.y, q3.x);
            OST(27, 7, q2.x, q2.y, q3.x, q3.y);
        }
    }
}

extern "C" void kernel_launch(void* const* d_in, const int* in_sizes, int n_in,
                              void* d_out, int out_size)
{
    const float* curr = (const float*)d_in[0];
    const float* prev = (const float*)d_in[1];
    float* out = (float*)d_out;

    cudaFuncSetAttribute(corr_kernel, cudaFuncAttributeMaxDynamicSharedMemorySize, SMEM_BYTES);

    dim3 grid(WW / TILE_W, HH / TILE_H, BB);   // 6 x 8 x 8 = 384 blocks
    corr_kernel<<<grid, NT, SMEM_BYTES>>>(curr, prev, out);
}